// round 16
// baseline (speedup 1.0000x reference)
#include <cuda_runtime.h>
#include <cstdint>
typedef unsigned long long ull;

__device__ float g_bufA[16 * 64 * 128 * 128];
__device__ float g_bufB[16 * 128 * 64 * 64];
__device__ float g_bufC[16 * 128 * 64 * 64];
__device__ float g_bufT[16 * 32 * 64 * 64];
__device__ float g_bufZ[16 * 64 * 64 * 64];
__device__ float g_bufQ[16 * 64 * 64 * 64];
__device__ float g_bufS[16 * 256 * 64 * 64];   // L1 s2d; later reused as record buf pR
__device__ __align__(16) unsigned short g_wb[1638400];

// ---------------- helpers ----------------
__device__ __forceinline__ ull pk2(float lo, float hi) {
    ull r; asm("mov.b64 %0, {%1, %2};" : "=l"(r) : "f"(lo), "f"(hi)); return r;
}
__device__ __forceinline__ void fma2(ull& a, ull v, ull w) {
    asm("fma.rn.f32x2 %0, %1, %2, %0;" : "+l"(a) : "l"(v), "l"(w));
}
__device__ __forceinline__ float2 upk(ull v) {
    float2 r; asm("mov.b64 {%0, %1}, %2;" : "=f"(r.x), "=f"(r.y) : "l"(v)); return r;
}
__device__ __forceinline__ void cpa4(uint32_t s, const float* g, bool ok) {
    asm volatile("cp.async.ca.shared.global [%0], [%1], 4, %2;" :: "r"(s), "l"(g), "r"(ok ? 4u : 0u));
}
__device__ __forceinline__ void cpa16(uint32_t s, const void* g) {
    asm volatile("cp.async.cg.shared.global [%0], [%1], 16;" :: "r"(s), "l"(g));
}
__device__ __forceinline__ void cpa16z(uint32_t s, const void* g, bool ok) {
    asm volatile("cp.async.cg.shared.global [%0], [%1], 16, %2;" :: "r"(s), "l"(g), "r"(ok ? 16u : 0u));
}
__device__ __forceinline__ void cpacommit() { asm volatile("cp.async.commit_group;"); }
template <int NN> __device__ __forceinline__ void cpawait() {
    asm volatile("cp.async.wait_group %0;" :: "n"(NN));
}
__device__ __forceinline__ uint32_t s2u(const void* p) { return (uint32_t)__cvta_generic_to_shared(p); }
__device__ __forceinline__ void ldsm4(uint32_t* r, uint32_t a) {
    asm volatile("ldmatrix.sync.aligned.m8n8.x4.shared.b16 {%0,%1,%2,%3}, [%4];"
                 : "=r"(r[0]), "=r"(r[1]), "=r"(r[2]), "=r"(r[3]) : "r"(a));
}
__device__ __forceinline__ void mma16816(float* c, const uint32_t* a, uint32_t b0, uint32_t b1) {
    asm volatile("mma.sync.aligned.m16n8k16.row.col.f32.bf16.bf16.f32 "
                 "{%0,%1,%2,%3}, {%4,%5,%6,%7}, {%8,%9}, {%0,%1,%2,%3};"
                 : "+f"(c[0]), "+f"(c[1]), "+f"(c[2]), "+f"(c[3])
                 : "r"(a[0]), "r"(a[1]), "r"(a[2]), "r"(a[3]), "r"(b0), "r"(b1));
}
__device__ __forceinline__ uint32_t bfsplit2(float x0, float x1, uint32_t& lopair) {
    unsigned short h0, h1, l0, l1; float f0, f1;
    asm("cvt.rn.bf16.f32 %0, %1;" : "=h"(h0) : "f"(x0));
    asm("cvt.f32.bf16 %0, %1;" : "=f"(f0) : "h"(h0));
    asm("cvt.rn.bf16.f32 %0, %1;" : "=h"(l0) : "f"(x0 - f0));
    asm("cvt.rn.bf16.f32 %0, %1;" : "=h"(h1) : "f"(x1));
    asm("cvt.f32.bf16 %0, %1;" : "=f"(f1) : "h"(h1));
    asm("cvt.rn.bf16.f32 %0, %1;" : "=h"(l1) : "f"(x1 - f1));
    lopair = (uint32_t)l0 | ((uint32_t)l1 << 16);
    return (uint32_t)h0 | ((uint32_t)h1 << 16);
}

__host__ __device__ constexpr int cmma_smem(int CO, int T, int PADK, int MW) {
    int PIX = (MW * 32 / 64 + 2 * PADK) * (64 + 2 * PADK);
    return (((PIX * 80 + 127) & ~127)) + 2 * T * CO * 80;
}

// ---------------------------------------------------------------------------
// Weight preps: record per (chunk, tap): CO recs x 80B = [16 hi][16 lo]
// ---------------------------------------------------------------------------
struct PrepJob { const float* w; int off; int CI; int CO; int KS; int total; };
struct PrepJobs { PrepJob j[11]; };

__global__ void prepw_all(PrepJobs jobs, unsigned short* __restrict__ dstbase)
{
    const PrepJob J = jobs.j[blockIdx.y];
    int i = blockIdx.x * 256 + threadIdx.x;
    if (i >= J.total) return;
    unsigned short* dst = dstbase + J.off;
    const int TT = J.KS * J.KS;
    const int kp = i & 7;
    int rest = i >> 3;
    const int n = rest % J.CO; rest /= J.CO;
    const int t = rest % TT;
    const int c = rest / TT;
    const int ci = c * 16 + 2 * kp;
    const float* base = J.w + (((long)n * J.CI + ci) * TT) + t;
    const float x0 = base[0], x1 = base[TT];
    uint32_t lo, hi = bfsplit2(x0, x1, lo);
    unsigned short* rec = dst + ((long)(c * TT + t) * J.CO + n) * 40;
    *(uint32_t*)(rec + 2 * kp) = hi;
    *(uint32_t*)(rec + 16 + 2 * kp) = lo;
}

__global__ void prepw_s2d(const float* __restrict__ w, unsigned short* __restrict__ dst)
{
    int i = blockIdx.x * 256 + threadIdx.x;
    if (i >= 65536) return;
    const int kp = i & 7;
    int rest = i >> 3;
    const int co = rest & 127; rest >>= 7;
    const int t = rest & 3;
    const int c = rest >> 2;
    const int p = c >> 2, py = p >> 1, px = p & 1;
    const int kh = 2 * (t >> 1) + 1 - py, kw = 2 * (t & 1) + 1 - px;
    const int ci = (c & 3) * 16 + 2 * kp;
    const float* s = w + (((long)co * 64 + ci) * 16) + kh * 4 + kw;
    uint32_t lo, hi = bfsplit2(s[0], s[16], lo);
    unsigned short* rec = dst + ((long)(c * 4 + t) * 128 + co) * 40;
    *(uint32_t*)(rec + 2 * kp) = hi;
    *(uint32_t*)(rec + 16 + 2 * kp) = lo;
}
__global__ void prepw_ct(const float* __restrict__ w, unsigned short* __restrict__ dst)
{
    int i = blockIdx.x * 256 + threadIdx.x;
    if (i >= 65536) return;
    const int kp = i & 7;
    int rest = i >> 3;
    const int co = rest & 63; rest >>= 6;
    const int t = rest & 3; rest >>= 2;
    const int c = rest & 7;
    const int ph = rest >> 3;
    const int ky = 2 * (t >> 1) + 1 - (ph >> 1), kx = 2 * (t & 1) + 1 - (ph & 1);
    const int ci = c * 16 + 2 * kp;
    const float* s = w + (((long)ci * 64 + co) * 16) + ky * 4 + kx;
    uint32_t lo, hi = bfsplit2(s[0], s[1024], lo);
    unsigned short* rec = dst + ((long)((ph * 8 + c) * 4 + t) * 64 + co) * 40;
    *(uint32_t*)(rec + 2 * kp) = hi;
    *(uint32_t*)(rec + 16 + 2 * kp) = lo;
}

// ---------------------------------------------------------------------------
// Generic legacy-MMA conv on 64x64 index space.
// MODE 0: stride-1 KSxKS; MODE 1: s2d stride-2 4x4 (L2); MODE 2: convT (up0).
// AIREC: input is split-bf16 records [n][CI/16][4096][64B] (RIN must be false).
// AOUT: 0 = planar only; 1 = record only (post-ROUT value);
//       2 = dual: planar v + record of relu(v).
// ---------------------------------------------------------------------------
template <int MODE, int CI, int CO, int KS, int MW, int NW, int OCC,
          bool RIN, bool ROUT, bool ADD, bool AIREC, int AOUT>
__global__ void __launch_bounds__(256, OCC) convmma(
    const float* __restrict__ in, const unsigned short* __restrict__ wb,
    const float* __restrict__ bias, const float* __restrict__ res,
    float* __restrict__ out, unsigned short* __restrict__ outrec)
{
    constexpr int CH = CI / 16;
    constexpr int T = (MODE == 0) ? KS * KS : 4;
    constexpr int PADK = (MODE == 0) ? (KS - 1) / 2 : 1;
    constexpr int MC = MW * 32;
    constexpr int NWT = CO / NW;
    constexpr int NB = NWT / 16;
    constexpr int YR = MC / 64 + 2 * PADK;
    constexpr int XW = 64 + 2 * PADK;
    constexpr int PIX = YR * XW;
    constexpr int ABYTES = (PIX * 80 + 127) & ~127;
    constexpr int BSTAGE = T * CO * 80;
    static_assert(!(AIREC && RIN), "record input cannot fuse relu");

    extern __shared__ char sm[];
    char* Abuf = sm;
    const uint32_t smA = s2u(sm);
    const uint32_t smB = s2u(sm + ABYTES);
    const int tid = threadIdx.x;
    const int lane = tid & 31;
    const int warp = tid >> 5;
    const int wm = (NW == 1) ? warp : (warp & (MW - 1));
    const int wn = (NW == 1) ? 0 : (warp >> 2);
    const int py = (MODE == 2) ? ((int)blockIdx.y >> 1) : 0;
    const int px = (MODE == 2) ? ((int)blockIdx.y & 1) : 0;
    const unsigned short* wbp = (MODE == 2) ? wb + (long)blockIdx.y * CH * T * CO * 40 : wb;
    const int mtile = blockIdx.x * MC;
    const int nimg = mtile >> 12;
    const int y0 = (mtile >> 6) & 63;
    const float* inb = in + ((long)nimg * CI << 12);
    const unsigned short* inrb = (const unsigned short*)in + ((long)nimg * CH << 12) * 32;
    const int q = lane >> 3, r = lane & 7;
    const int m_off = ((q & 1) << 3) + r;
    const int k8b = (q >> 1) * 16;

    uint32_t laneA[2];
#pragma unroll
    for (int im = 0; im < 2; im++) {
        const int mrow = wm * 32 + im * 16 + m_off;
        laneA[im] = smA + (uint32_t)((mrow >> 6) * XW + (mrow & 63)) * 80 + k8b;
    }
    const uint32_t laneBoff = (uint32_t)(wn * NWT + m_off) * 80 + k8b;

    float acc[2][2 * NB][4];
#pragma unroll
    for (int im = 0; im < 2; im++)
#pragma unroll
        for (int j = 0; j < 2 * NB; j++)
#pragma unroll
            for (int e = 0; e < 4; e++) acc[im][j][e] = 0.f;

    auto stageBall = [&](int c, int b) {
        const char* src = (const char*)(wbp + (long)c * T * CO * 40);
        const uint32_t d = smB + (uint32_t)b * BSTAGE;
        for (int i = tid; i < T * CO * 5; i += 256)
            cpa16(d + (uint32_t)i * 16, src + (long)i * 16);
    };
    auto stageA = [&](int c) {
        if (AIREC) {
            const unsigned short* cb = inrb + ((long)c << 12) * 32;
            for (int i = tid; i < PIX * 4; i += 256) {
                const int p = i >> 2, sub = i & 3;
                const int yy = p / XW, xx = p - yy * XW;
                const int iy = y0 + yy - PADK, ix = xx - PADK;
                const bool ok = (iy >= 0) & (iy < 64) & (ix >= 0) & (ix < 64);
                const char* src = (const char*)(cb + (long)(ok ? iy * 64 + ix : 0) * 32) + sub * 16;
                cpa16z(smA + (uint32_t)p * 80 + (uint32_t)sub * 16, src, ok);
            }
        } else {
            const int ci0 = c * 16;
            for (int i = tid; i < 8 * PIX; i += 256) {
                const int cp = i / PIX, p = i - cp * PIX;
                const int yy = p / XW, xx = p - yy * XW;
                const int iy = y0 + yy - PADK, ix = xx - PADK;
                float v0 = 0.f, v1 = 0.f;
                if (iy >= 0 && iy < 64 && ix >= 0 && ix < 64) {
                    const float* pp = inb + ((long)(ci0 + 2 * cp) << 12) + (iy << 6) + ix;
                    v0 = __ldg(pp); v1 = __ldg(pp + 4096);
                }
                if (RIN) { v0 = fmaxf(v0, 0.f); v1 = fmaxf(v1, 0.f); }
                uint32_t lo, hi = bfsplit2(v0, v1, lo);
                *(uint32_t*)(Abuf + p * 80 + 4 * cp) = hi;
                *(uint32_t*)(Abuf + p * 80 + 32 + 4 * cp) = lo;
            }
        }
    };

    stageBall(0, 0);
    cpacommit();
    for (int c = 0; c < CH; c++) {
        __syncthreads();
        if (AIREC) {
            stageA(c);
            cpacommit();
            if (c + 1 < CH) { stageBall(c + 1, (c + 1) & 1); cpacommit(); }
        } else {
            if (c + 1 < CH) { stageBall(c + 1, (c + 1) & 1); cpacommit(); }
            stageA(c);
        }
        if (c + 1 < CH) cpawait<1>(); else cpawait<0>();
        __syncthreads();
        const uint32_t bstage = smB + (uint32_t)(c & 1) * BSTAGE;
#pragma unroll 1
        for (int t = 0; t < T; t++) {
            int dyr, dxr;
            if (MODE == 0) { dyr = t / KS; dxr = t - (t / KS) * KS; }
            else if (MODE == 1) {
                const int pc = c >> 2;
                dyr = (t >> 1) - (pc >> 1) + 1;
                dxr = (t & 1) - (pc & 1) + 1;
            } else {
                dyr = py - (t >> 1) + 1;
                dxr = px - (t & 1) + 1;
            }
            const uint32_t dt = (uint32_t)(dyr * XW + dxr) * 80;
            uint32_t ah[2][4], al[2][4];
            ldsm4(ah[0], laneA[0] + dt);
            ldsm4(ah[1], laneA[1] + dt);
            ldsm4(al[0], laneA[0] + dt + 32);
            ldsm4(al[1], laneA[1] + dt + 32);
            const uint32_t bb = bstage + (uint32_t)t * (CO * 80) + laneBoff;
            uint32_t bf[NB][4];
#pragma unroll
            for (int nb = 0; nb < NB; nb++) ldsm4(bf[nb], bb + (uint32_t)nb * 1280);
#pragma unroll
            for (int im = 0; im < 2; im++)
#pragma unroll
                for (int nb = 0; nb < NB; nb++) {
                    mma16816(acc[im][2 * nb], ah[im], bf[nb][0], bf[nb][2]);
                    mma16816(acc[im][2 * nb + 1], ah[im], bf[nb][1], bf[nb][3]);
                    mma16816(acc[im][2 * nb], al[im], bf[nb][0], bf[nb][2]);
                    mma16816(acc[im][2 * nb + 1], al[im], bf[nb][1], bf[nb][3]);
                }
#pragma unroll
            for (int nb = 0; nb < NB; nb++) ldsm4(bf[nb], bb + (uint32_t)nb * 1280 + 32);
#pragma unroll
            for (int im = 0; im < 2; im++)
#pragma unroll
                for (int nb = 0; nb < NB; nb++) {
                    mma16816(acc[im][2 * nb], ah[im], bf[nb][0], bf[nb][2]);
                    mma16816(acc[im][2 * nb + 1], ah[im], bf[nb][1], bf[nb][3]);
                }
        }
    }

    const int gid = lane >> 2, tg = lane & 3;
    const int l0 = (mtile & 4095) + wm * 32 + gid;
#pragma unroll
    for (int im = 0; im < 2; im++) {
#pragma unroll
        for (int j = 0; j < 2 * NB; j++) {
            const int col = wn * NWT + j * 8 + 2 * tg;
            const float b0 = __ldg(bias + col), b1 = __ldg(bias + col + 1);
#pragma unroll
            for (int h = 0; h < 2; h++) {
                const int sp = l0 + im * 16 + h * 8;
                float v0 = acc[im][j][2 * h] + b0;
                float v1 = acc[im][j][2 * h + 1] + b1;
                if (MODE == 2) {
                    if (ROUT) { v0 = fmaxf(v0, 0.f); v1 = fmaxf(v1, 0.f); }
                    const long cb2 = ((long)nimg * CO + col) << 14;
                    const int oo = (((sp >> 6) * 2 + py) << 7) + ((sp & 63) * 2 + px);
                    out[cb2 + oo] = v0;
                    out[cb2 + oo + 16384] = v1;
                } else {
                    const long o0 = (((long)nimg * CO + col) << 12) + sp;
                    if (ADD) { v0 += __ldg(res + o0); v1 += __ldg(res + o0 + 4096); }
                    if (ROUT) { v0 = fmaxf(v0, 0.f); v1 = fmaxf(v1, 0.f); }
                    if (AOUT != 1) {
                        out[o0] = v0;
                        out[o0 + 4096] = v1;
                    }
                    if (AOUT >= 1) {
                        float r0 = v0, r1 = v1;
                        if (AOUT == 2) { r0 = fmaxf(r0, 0.f); r1 = fmaxf(r1, 0.f); }
                        const int ch = col >> 4, cl = col & 15;
                        unsigned short* rec = outrec +
                            ((((long)nimg * (CO / 16) + ch) << 12) + sp) * 32;
                        uint32_t lo2, hi2 = bfsplit2(r0, r1, lo2);
                        *(uint32_t*)(rec + cl) = hi2;
                        *(uint32_t*)(rec + 16 + cl) = lo2;
                    }
                }
            }
        }
    }
}

// ---------------------------------------------------------------------------
// L1 fp32 conv (CI=3), s2d output; 4x4/s2, OW=128, OHB=4.
// ---------------------------------------------------------------------------
__global__ void __launch_bounds__(256) conv_l1(
    const float* __restrict__ in, const float* __restrict__ wt,
    const float* __restrict__ bias, float* __restrict__ out)
{
    constexpr int TWIDP = 260, TILE_CI = 2600, TILE = 7800, WSTR = 49;
    extern __shared__ char smx[];
    float* tile = (float*)smx;
    ull* wp = (ull*)(smx + TILE * 4);
    const int n = blockIdx.x >> 5, rb = blockIdx.x & 31;
    const int oy0 = rb * 4, co0 = blockIdx.y * 16;
    const int tid = threadIdx.x, cog = tid & 3, spat = tid >> 2;
    const int owg = spat & 15, ohr = spat >> 4;
    const int co_l = cog * 4;
    const int iy0 = oy0 * 2 - 1;
    const float* inn = in + (long)n * 3 * 65536;

    ull acc[4][4];
#pragma unroll
    for (int c = 0; c < 4; c++) {
        const float b = __ldg(bias + co0 + co_l + c);
        const ull bb = pk2(b, b);
#pragma unroll
        for (int m = 0; m < 4; m++) acc[c][m] = bb;
    }
    {
        const uint32_t tadr = s2u(tile);
        for (int i = tid; i < TILE; i += 256) {
            const int ci_l = i / TILE_CI;
            const int rem = i - ci_l * TILE_CI;
            const int rr = rem / TWIDP, c = rem - rr * TWIDP;
            const int iy = iy0 + rr, ix = c - 1;
            const bool ok = (c < 258) & (iy >= 0) & (iy < 256) & (ix >= 0) & (ix < 256);
            const float* src = ok ? inn + ((long)ci_l * 256 + iy) * 256 + ix : inn;
            cpa4(tadr + 4u * (uint32_t)i, src, ok);
        }
        for (int i = tid; i < 16 * 48; i += 256) {
            const int c = i / 48, rem = i - c * 48;
            const float w = __ldg(wt + ((long)(co0 + c) * 3 + rem / 16) * 16 + rem % 16);
            wp[c * WSTR + rem] = pk2(w, w);
        }
        cpacommit(); cpawait<0>();
        __syncthreads();
    }
#pragma unroll 1
    for (int ci_l = 0; ci_l < 3; ci_l++) {
        const float* tci = tile + ci_l * TILE_CI;
#pragma unroll
        for (int kh = 0; kh < 4; kh++) {
            const float* trow = tci + (ohr * 2 + kh) * TWIDP + owg * 16;
            float ir[18];
#pragma unroll
            for (int v = 0; v < 4; v++) {
                const float4 q4 = reinterpret_cast<const float4*>(trow)[v];
                ir[4 * v] = q4.x; ir[4 * v + 1] = q4.y; ir[4 * v + 2] = q4.z; ir[4 * v + 3] = q4.w;
            }
            ir[16] = trow[16]; ir[17] = trow[17];
#pragma unroll
            for (int kw = 0; kw < 4; kw++) {
                ull p[4];
#pragma unroll
                for (int m = 0; m < 4; m++)
                    p[m] = pk2(ir[4 * m + kw], ir[4 * m + 2 + kw]);
#pragma unroll
                for (int c = 0; c < 4; c++) {
                    const ull w2 = wp[(co_l + c) * WSTR + ci_l * 16 + kh * 4 + kw];
#pragma unroll
                    for (int m = 0; m < 4; m++) fma2(acc[c][m], p[m], w2);
                }
            }
        }
    }
    const int oy = oy0 + ohr;
#pragma unroll
    for (int c = 0; c < 4; c++) {
        float o[8];
#pragma unroll
        for (int m = 0; m < 4; m++) {
            const float2 t = upk(acc[c][m]);
            o[2 * m] = fmaxf(t.x, 0.f); o[2 * m + 1] = fmaxf(t.y, 0.f);
        }
        const int pyl = oy & 1, yh = oy >> 1, xh0 = owg * 4;
        const int ch = co0 + co_l + c;
        float* p0 = out + (((long)n * 256 + (pyl * 2 + 0) * 64 + ch) << 12) + (yh << 6) + xh0;
        float* p1 = out + (((long)n * 256 + (pyl * 2 + 1) * 64 + ch) << 12) + (yh << 6) + xh0;
        *reinterpret_cast<float4*>(p0) = make_float4(o[0], o[2], o[4], o[6]);
        *reinterpret_cast<float4*>(p1) = make_float4(o[1], o[3], o[5], o[7]);
    }
}

// ---------------------------------------------------------------------------
// up1 fp32 conv-T (64 -> 3, 128->256)
// ---------------------------------------------------------------------------
__global__ void __launch_bounds__(256) convt_up1(
    const float* __restrict__ in, const float* __restrict__ wt,
    const float* __restrict__ bias, float* __restrict__ out)
{
    constexpr int TWIDP = 132, TILE_CI = 792, TILE = 6336, WTSTR = 129;
    constexpr int STRIDEB = TILE * 4 + 2 * WTSTR * 8;
    extern __shared__ char smx[];
    const int n = blockIdx.x >> 5, rb = blockIdx.x & 31;
    const int oy0 = rb * 8;
    const int tid = threadIdx.x;
    const int owg = tid & 31, ohr = tid >> 5;
    const int iy0 = oy0 / 2 - 1;
    const int oy = oy0 + ohr;
    const int ky0 = (oy + 1) & 1;
    const float* inn = in + (long)n * 64 * 16384;

    ull accp[2][8];
#pragma unroll
    for (int qq = 0; qq < 2; qq++) {
        const int c0 = 2 * qq;
        const float b0 = (c0 < 3) ? __ldg(bias + c0) : 0.f;
        const float b1 = (c0 + 1 < 3) ? __ldg(bias + c0 + 1) : 0.f;
        const ull bb = pk2(b0, b1);
#pragma unroll
        for (int j = 0; j < 8; j++) accp[qq][j] = bb;
    }
    auto stage = [&](int gidx, int bi) {
        char* buf = smx + bi * STRIDEB;
        float* tile = (float*)buf;
        ull* wp = (ull*)(buf + TILE * 4);
        const uint32_t tadr = s2u(tile);
        const int ci0 = gidx * 8;
        for (int i = tid; i < TILE; i += 256) {
            const int ci_l = i / TILE_CI;
            const int rem = i - ci_l * TILE_CI;
            const int rr = rem / TWIDP, c = rem - rr * TWIDP;
            const int iy = iy0 + rr, ix = c - 1;
            const bool ok = (c < 130) & (iy >= 0) & (iy < 128) & (ix >= 0) & (ix < 128);
            const float* src = ok ? inn + ((long)(ci0 + ci_l) * 128 + iy) * 128 + ix : inn;
            cpa4(tadr + 4u * (uint32_t)i, src, ok);
        }
        for (int i = tid; i < 2 * 128; i += 256) {
            const int cpg = i >> 7, rem = i & 127;
            const int ci_l = rem >> 4, tap = rem & 15;
            const int c0 = 2 * cpg;
            const float w0 = (c0 < 3) ? __ldg(wt + ((long)(ci0 + ci_l) * 3 + c0) * 16 + tap) : 0.f;
            const float w1 = (c0 + 1 < 3) ? __ldg(wt + ((long)(ci0 + ci_l) * 3 + c0 + 1) * 16 + tap) : 0.f;
            wp[cpg * WTSTR + rem] = pk2(w0, w1);
        }
    };
    stage(0, 0);
    cpacommit();
    for (int g = 0; g < 8; g++) {
        const int bi = g & 1;
        if (g + 1 < 8) { stage(g + 1, bi ^ 1); cpacommit(); cpawait<1>(); }
        else cpawait<0>();
        __syncthreads();
        const float* tb = (const float*)(smx + bi * STRIDEB);
        const ull* wbp = (const ull*)(smx + bi * STRIDEB + TILE * 4);
#pragma unroll 1
        for (int ci_l = 0; ci_l < 8; ci_l++) {
            const float* tci = tb + ci_l * TILE_CI;
#pragma unroll
            for (int t2 = 0; t2 < 2; t2++) {
                const int ky = ky0 + 2 * t2;
                const int rr = ((oy + 1 - ky) >> 1) - iy0;
                const float* trow = tci + rr * TWIDP + owg * 4;
                float ir[6];
                {
                    const float4 q4 = *reinterpret_cast<const float4*>(trow);
                    ir[0] = q4.x; ir[1] = q4.y; ir[2] = q4.z; ir[3] = q4.w;
                    ir[4] = trow[4]; ir[5] = trow[5];
                }
#pragma unroll
                for (int kx = 0; kx < 4; kx++) {
                    const int ph = (kx + 1) & 1;
                    const int dt = (kx == 0) ? 1 : ((kx == 3) ? -1 : 0);
                    ull vv[4];
#pragma unroll
                    for (int m = 0; m < 4; m++) {
                        const float v = ir[m + dt + 1];
                        vv[m] = pk2(v, v);
                    }
#pragma unroll
                    for (int qq = 0; qq < 2; qq++) {
                        const ull w2 = wbp[qq * WTSTR + ci_l * 16 + ky * 4 + kx];
#pragma unroll
                        for (int m = 0; m < 4; m++) fma2(accp[qq][2 * m + ph], vv[m], w2);
                    }
                }
            }
        }
        __syncthreads();
    }
#pragma unroll
    for (int qq = 0; qq < 2; qq++) {
        float o0[8], o1[8];
#pragma unroll
        for (int j = 0; j < 8; j++) {
            const float2 t = upk(accp[qq][j]);
            o0[j] = t.x; o1[j] = t.y;
        }
        const int c0 = 2 * qq, c1 = c0 + 1;
        if (c0 < 3) {
            float* op = out + (((long)n * 3 + c0) * 256 + oy) * 256 + owg * 8;
            reinterpret_cast<float4*>(op)[0] = make_float4(o0[0], o0[1], o0[2], o0[3]);
            reinterpret_cast<float4*>(op)[1] = make_float4(o0[4], o0[5], o0[6], o0[7]);
        }
        if (c1 < 3) {
            float* op = out + (((long)n * 3 + c1) * 256 + oy) * 256 + owg * 8;
            reinterpret_cast<float4*>(op)[0] = make_float4(o1[0], o1[1], o1[2], o1[3]);
            reinterpret_cast<float4*>(op)[1] = make_float4(o1[4], o1[5], o1[6], o1[7]);
        }
    }
}

// ---------------------------------------------------------------------------
// VQ
// ---------------------------------------------------------------------------
__global__ void __launch_bounds__(256) vqk2(
    const float* __restrict__ z, const float* __restrict__ cb, float* __restrict__ q)
{
    constexpr int NPIX = 4096;
    __shared__ float cbs[128][68];
    __shared__ float cns[128];
    const int tid = threadIdx.x;
    const int p = blockIdx.x * 256 + tid;
    const int b = p >> 12;
    const int pix = p & 4095;
    const float* zp = z + (long)b * 64 * NPIX + pix;
    float f[64];
#pragma unroll
    for (int d = 0; d < 64; d++) f[d] = zp[(long)d * NPIX];
    ull fp[32];
#pragma unroll
    for (int i = 0; i < 32; i++) fp[i] = pk2(f[2 * i], f[2 * i + 1]);
    float best = 3.4e38f;
    int bidx = 0;
    for (int t = 0; t < 4; t++) {
        __syncthreads();
        for (int i = tid; i < 8192; i += 256) {
            const int d = i >> 7, kk = i & 127;
            cbs[kk][d] = __ldg(cb + d * 512 + t * 128 + kk);
        }
        __syncthreads();
        if (tid < 128) {
            const float* row = cbs[tid];
            float s = 0.f;
#pragma unroll
            for (int d = 0; d < 64; d++) s += row[d] * row[d];
            cns[tid] = s;
        }
        __syncthreads();
        for (int kk = 0; kk < 128; kk++) {
            const ulonglong2* row = reinterpret_cast<const ulonglong2*>(cbs[kk]);
            ull a0 = 0, a1 = 0, a2 = 0, a3 = 0;
#pragma unroll
            for (int i = 0; i < 16; i += 2) {
                const ulonglong2 u = row[i];
                const ulonglong2 v = row[i + 1];
                fma2(a0, u.x, fp[2 * i]);
                fma2(a1, u.y, fp[2 * i + 1]);
                fma2(a2, v.x, fp[2 * i + 2]);
                fma2(a3, v.y, fp[2 * i + 3]);
            }
            const float2 x0 = upk(a0), x1 = upk(a1), x2 = upk(a2), x3 = upk(a3);
            const float dot = ((x0.x + x0.y) + (x1.x + x1.y)) + ((x2.x + x2.y) + (x3.x + x3.y));
            const float dist = cns[kk] - 2.f * dot;
            if (dist < best) { best = dist; bidx = t * 128 + kk; }
        }
    }
    float* qp = q + (long)b * 64 * NPIX + pix;
#pragma unroll
    for (int d = 0; d < 64; d++) qp[(long)d * NPIX] = __ldg(cb + d * 512 + bidx);
}

// ---------------------------------------------------------------------------
// Host launcher
// ---------------------------------------------------------------------------
extern "C" void kernel_launch(void* const* d_in, const int* in_sizes, int n_in,
                              void* d_out, int out_size)
{
    (void)in_sizes; (void)n_in; (void)out_size;
    const float* x        = (const float*)d_in[0];
    const float* enc_w0   = (const float*)d_in[1];
    const float* enc_b0   = (const float*)d_in[2];
    const float* enc_w1   = (const float*)d_in[3];
    const float* enc_b1   = (const float*)d_in[4];
    const float* enc_wf   = (const float*)d_in[5];
    const float* enc_bf   = (const float*)d_in[6];
    const float* enc_rw1  = (const float*)d_in[7];
    const float* enc_rb1  = (const float*)d_in[8];
    const float* enc_rw2  = (const float*)d_in[9];
    const float* enc_rb2  = (const float*)d_in[10];
    const float* pre_w    = (const float*)d_in[11];
    const float* pre_b    = (const float*)d_in[12];
    const float* codebook = (const float*)d_in[13];
    const float* dec_w    = (const float*)d_in[14];
    const float* dec_b    = (const float*)d_in[15];
    const float* dec_rw1  = (const float*)d_in[16];
    const float* dec_rb1  = (const float*)d_in[17];
    const float* dec_rw2  = (const float*)d_in[18];
    const float* dec_rb2  = (const float*)d_in[19];
    const float* up_w0    = (const float*)d_in[20];
    const float* up_b0    = (const float*)d_in[21];
    const float* up_w1    = (const float*)d_in[22];
    const float* up_b1    = (const float*)d_in[23];
    float* out = (float*)d_out;

    float *pA, *pB, *pC, *pT, *pZ, *pQ, *pS;
    unsigned short* pW;
    cudaGetSymbolAddress((void**)&pA, g_bufA);
    cudaGetSymbolAddress((void**)&pB, g_bufB);
    cudaGetSymbolAddress((void**)&pC, g_bufC);
    cudaGetSymbolAddress((void**)&pT, g_bufT);
    cudaGetSymbolAddress((void**)&pZ, g_bufZ);
    cudaGetSymbolAddress((void**)&pQ, g_bufQ);
    cudaGetSymbolAddress((void**)&pS, g_bufS);
    cudaGetSymbolAddress((void**)&pW, g_wb);
    unsigned short* pR = (unsigned short*)pS;   // record buffer (reuses bufS after L2)
    unsigned short* pBr = (unsigned short*)pB;  // L2 writes records directly into pB
    unsigned short* pTr = (unsigned short*)pT;

    // g_wb offsets (shorts)
    const int oWF = 0;
    const int oER1a = 368640, oER1b = 460800;
    const int oER2a = 552960, oER2b = 563200;
    const int oPRE = 573440;
    const int oDEC = 593920;
    const int oDR1a = 778240, oDR1b = 870400;
    const int oDR2a = 962560, oDR2b = 972800;
    const int oL2  = 983040;
    const int oUP0 = 1310720;

    cudaFuncSetAttribute((const void*)convmma<1,256,128,0,4,2,2,false,true,false,false,1>,
        cudaFuncAttributeMaxDynamicSharedMemorySize, cmma_smem(128,4,1,4));
    cudaFuncSetAttribute((const void*)convmma<0,128,128,3,4,2,1,false,false,false,true,2>,
        cudaFuncAttributeMaxDynamicSharedMemorySize, cmma_smem(128,9,1,4));
    cudaFuncSetAttribute((const void*)convmma<0,64,128,3,4,2,1,false,false,false,false,2>,
        cudaFuncAttributeMaxDynamicSharedMemorySize, cmma_smem(128,9,1,4));
    cudaFuncSetAttribute((const void*)convmma<0,128,32,3,8,1,2,false,true,false,true,1>,
        cudaFuncAttributeMaxDynamicSharedMemorySize, cmma_smem(32,9,1,8));
    cudaFuncSetAttribute((const void*)convmma<2,128,64,0,4,2,2,false,true,false,true,0>,
        cudaFuncAttributeMaxDynamicSharedMemorySize, cmma_smem(64,4,1,4));
    cudaFuncSetAttribute((const void*)convt_up1,
        cudaFuncAttributeMaxDynamicSharedMemorySize, 2 * (6336*4 + 2*129*8));

    // batched weight prep
    PrepJobs jobs;
    auto J = [&](int k, const float* w, int off, int CI, int CO, int KS) {
        jobs.j[k] = PrepJob{w, off, CI, CO, KS, (CI / 16) * KS * KS * CO * 8};
    };
    J(0, enc_wf, oWF, 128, 128, 3);
    J(1, enc_rw1, oER1a, 128, 32, 3);
    J(2, enc_rw1 + (long)32 * 128 * 9, oER1b, 128, 32, 3);
    J(3, enc_rw2, oER2a, 32, 128, 1);
    J(4, enc_rw2 + (long)128 * 32, oER2b, 32, 128, 1);
    J(5, pre_w, oPRE, 128, 64, 1);
    J(6, dec_w, oDEC, 64, 128, 3);
    J(7, dec_rw1, oDR1a, 128, 32, 3);
    J(8, dec_rw1 + (long)32 * 128 * 9, oDR1b, 128, 32, 3);
    J(9, dec_rw2, oDR2a, 32, 128, 1);
    J(10, dec_rw2 + (long)128 * 32, oDR2b, 32, 128, 1);
    prepw_all<<<dim3(288, 11), 256>>>(jobs, pW);
    prepw_s2d<<<256, 256>>>(enc_w1, pW + oL2);
    prepw_ct<<<256, 256>>>(up_w0, pW + oUP0);

    // L1 fp32 -> s2d layout in bufS
    conv_l1<<<dim3(512, 4), 256, 7800*4 + 16*49*8>>>(x, enc_w0, enc_b0, pS);
    // L2 (s2d) -> pB records (relu fused)
    convmma<1,256,128,0,4,2,2,false,true,false,false,1><<<512, 256, cmma_smem(128,4,1,4)>>>(
        pS, pW + oL2, enc_b1, nullptr, pB, pBr);
    // enc_wf: record-in (pB) -> pC planar + pR record(relu)
    convmma<0,128,128,3,4,2,1,false,false,false,true,2><<<512, 256, cmma_smem(128,9,1,4)>>>(
        pB, pW + oWF, enc_bf, nullptr, pC, pR);
    // enc res blocks: 3x3 record-in (pR) relu-out -> pT record; 1x1 record-in + ADD -> dual
    convmma<0,128,32,3,8,1,2,false,true,false,true,1><<<256, 256, cmma_smem(32,9,1,8)>>>(
        (const float*)pR, pW + oER1a, enc_rb1, nullptr, pT, pTr);
    convmma<0,32,128,1,4,2,2,false,false,true,true,2><<<512, 256, cmma_smem(128,1,0,4)>>>(
        pT, pW + oER2a, enc_rb2, pC, pC, pR);
    convmma<0,128,32,3,8,1,2,false,true,false,true,1><<<256, 256, cmma_smem(32,9,1,8)>>>(
        (const float*)pR, pW + oER1b, enc_rb1 + 32, nullptr, pT, pTr);
    convmma<0,32,128,1,4,2,2,false,false,true,true,2><<<512, 256, cmma_smem(128,1,0,4)>>>(
        pT, pW + oER2b, enc_rb2 + 128, pC, pC, pR);
    // pre: record-in (pR) -> bufZ planar
    convmma<0,128,64,1,4,2,2,false,false,false,true,0><<<512, 256, cmma_smem(64,1,0,4)>>>(
        (const float*)pR, pW + oPRE, pre_b, nullptr, pZ, nullptr);

    vqk2<<<256, 256>>>(pZ, codebook, pQ);

    // dec conv (planar in) -> pB planar + pR record(relu)
    convmma<0,64,128,3,4,2,1,false,false,false,false,2><<<512, 256, cmma_smem(128,9,1,4)>>>(
        pQ, pW + oDEC, dec_b, nullptr, pB, pR);
    // dec res blocks
    convmma<0,128,32,3,8,1,2,false,true,false,true,1><<<256, 256, cmma_smem(32,9,1,8)>>>(
        (const float*)pR, pW + oDR1a, dec_rb1, nullptr, pT, pTr);
    convmma<0,32,128,1,4,2,2,false,false,true,true,2><<<512, 256, cmma_smem(128,1,0,4)>>>(
        pT, pW + oDR2a, dec_rb2, pB, pB, pR);
    convmma<0,128,32,3,8,1,2,false,true,false,true,1><<<256, 256, cmma_smem(32,9,1,8)>>>(
        (const float*)pR, pW + oDR1b, dec_rb1 + 32, nullptr, pT, pTr);
    convmma<0,32,128,1,4,2,2,false,false,true,true,2><<<512, 256, cmma_smem(128,1,0,4)>>>(
        pT, pW + oDR2b, dec_rb2 + 128, pB, pB, pR);
    // up0: record-in (pR), convT phases, relu-out -> bufA planar
    convmma<2,128,64,0,4,2,2,false,true,false,true,0><<<dim3(512, 4), 256, cmma_smem(64,4,1,4)>>>(
        (const float*)pR, pW + oUP0, up_b0, nullptr, pA, nullptr);
    // up1 fp32 -> out
    convt_up1<<<512, 256, 2 * (6336*4 + 2*129*8)>>>(pA, up_w1, up_b1, out);
}

// round 17
// speedup vs baseline: 1.5487x; 1.5487x over previous
#include <cuda_runtime.h>
#include <cstdint>
typedef unsigned long long ull;

__device__ float g_bufA[16 * 64 * 128 * 128];
__device__ float g_bufB[16 * 128 * 64 * 64];
__device__ float g_bufC[16 * 128 * 64 * 64];
__device__ float g_bufT[16 * 32 * 64 * 64];
__device__ float g_bufZ[16 * 64 * 64 * 64];
__device__ float g_bufQ[16 * 64 * 64 * 64];
__device__ float g_bufS[16 * 256 * 64 * 64];   // L1 s2d; later reused as record buf pR
__device__ __align__(16) unsigned short g_wb[1638400];

// ---------------- helpers ----------------
__device__ __forceinline__ ull pk2(float lo, float hi) {
    ull r; asm("mov.b64 %0, {%1, %2};" : "=l"(r) : "f"(lo), "f"(hi)); return r;
}
__device__ __forceinline__ void fma2(ull& a, ull v, ull w) {
    asm("fma.rn.f32x2 %0, %1, %2, %0;" : "+l"(a) : "l"(v), "l"(w));
}
__device__ __forceinline__ float2 upk(ull v) {
    float2 r; asm("mov.b64 {%0, %1}, %2;" : "=f"(r.x), "=f"(r.y) : "l"(v)); return r;
}
__device__ __forceinline__ void cpa4(uint32_t s, const float* g, bool ok) {
    asm volatile("cp.async.ca.shared.global [%0], [%1], 4, %2;" :: "r"(s), "l"(g), "r"(ok ? 4u : 0u));
}
__device__ __forceinline__ void cpa16(uint32_t s, const void* g) {
    asm volatile("cp.async.cg.shared.global [%0], [%1], 16;" :: "r"(s), "l"(g));
}
__device__ __forceinline__ void cpa16z(uint32_t s, const void* g, bool ok) {
    asm volatile("cp.async.cg.shared.global [%0], [%1], 16, %2;" :: "r"(s), "l"(g), "r"(ok ? 16u : 0u));
}
__device__ __forceinline__ void cpacommit() { asm volatile("cp.async.commit_group;"); }
template <int NN> __device__ __forceinline__ void cpawait() {
    asm volatile("cp.async.wait_group %0;" :: "n"(NN));
}
__device__ __forceinline__ uint32_t s2u(const void* p) { return (uint32_t)__cvta_generic_to_shared(p); }
__device__ __forceinline__ void ldsm4(uint32_t* r, uint32_t a) {
    asm volatile("ldmatrix.sync.aligned.m8n8.x4.shared.b16 {%0,%1,%2,%3}, [%4];"
                 : "=r"(r[0]), "=r"(r[1]), "=r"(r[2]), "=r"(r[3]) : "r"(a));
}
__device__ __forceinline__ void mma16816(float* c, const uint32_t* a, uint32_t b0, uint32_t b1) {
    asm volatile("mma.sync.aligned.m16n8k16.row.col.f32.bf16.bf16.f32 "
                 "{%0,%1,%2,%3}, {%4,%5,%6,%7}, {%8,%9}, {%0,%1,%2,%3};"
                 : "+f"(c[0]), "+f"(c[1]), "+f"(c[2]), "+f"(c[3])
                 : "r"(a[0]), "r"(a[1]), "r"(a[2]), "r"(a[3]), "r"(b0), "r"(b1));
}
__device__ __forceinline__ uint32_t bfsplit2(float x0, float x1, uint32_t& lopair) {
    unsigned short h0, h1, l0, l1; float f0, f1;
    asm("cvt.rn.bf16.f32 %0, %1;" : "=h"(h0) : "f"(x0));
    asm("cvt.f32.bf16 %0, %1;" : "=f"(f0) : "h"(h0));
    asm("cvt.rn.bf16.f32 %0, %1;" : "=h"(l0) : "f"(x0 - f0));
    asm("cvt.rn.bf16.f32 %0, %1;" : "=h"(h1) : "f"(x1));
    asm("cvt.f32.bf16 %0, %1;" : "=f"(f1) : "h"(h1));
    asm("cvt.rn.bf16.f32 %0, %1;" : "=h"(l1) : "f"(x1 - f1));
    lopair = (uint32_t)l0 | ((uint32_t)l1 << 16);
    return (uint32_t)h0 | ((uint32_t)h1 << 16);
}

__host__ __device__ constexpr int cmma_smem(int CO, int T, int PADK, int MW) {
    int PIX = (MW * 32 / 64 + 2 * PADK) * (64 + 2 * PADK);
    return (((PIX * 80 + 127) & ~127)) + 2 * T * CO * 80;
}

// ---------------------------------------------------------------------------
// Weight preps: record per (chunk, tap): CO recs x 80B = [16 hi][16 lo]
// ---------------------------------------------------------------------------
struct PrepJob { const float* w; int off; int CI; int CO; int KS; int total; };
struct PrepJobs { PrepJob j[11]; };

__global__ void prepw_all(PrepJobs jobs, unsigned short* __restrict__ dstbase)
{
    const PrepJob J = jobs.j[blockIdx.y];
    int i = blockIdx.x * 256 + threadIdx.x;
    if (i >= J.total) return;
    unsigned short* dst = dstbase + J.off;
    const int TT = J.KS * J.KS;
    const int kp = i & 7;
    int rest = i >> 3;
    const int n = rest % J.CO; rest /= J.CO;
    const int t = rest % TT;
    const int c = rest / TT;
    const int ci = c * 16 + 2 * kp;
    const float* base = J.w + (((long)n * J.CI + ci) * TT) + t;
    const float x0 = base[0], x1 = base[TT];
    uint32_t lo, hi = bfsplit2(x0, x1, lo);
    unsigned short* rec = dst + ((long)(c * TT + t) * J.CO + n) * 40;
    *(uint32_t*)(rec + 2 * kp) = hi;
    *(uint32_t*)(rec + 16 + 2 * kp) = lo;
}

__global__ void prepw_s2d(const float* __restrict__ w, unsigned short* __restrict__ dst)
{
    int i = blockIdx.x * 256 + threadIdx.x;
    if (i >= 65536) return;
    const int kp = i & 7;
    int rest = i >> 3;
    const int co = rest & 127; rest >>= 7;
    const int t = rest & 3;
    const int c = rest >> 2;
    const int p = c >> 2, py = p >> 1, px = p & 1;
    const int kh = 2 * (t >> 1) + 1 - py, kw = 2 * (t & 1) + 1 - px;
    const int ci = (c & 3) * 16 + 2 * kp;
    const float* s = w + (((long)co * 64 + ci) * 16) + kh * 4 + kw;
    uint32_t lo, hi = bfsplit2(s[0], s[16], lo);
    unsigned short* rec = dst + ((long)(c * 4 + t) * 128 + co) * 40;
    *(uint32_t*)(rec + 2 * kp) = hi;
    *(uint32_t*)(rec + 16 + 2 * kp) = lo;
}
__global__ void prepw_ct(const float* __restrict__ w, unsigned short* __restrict__ dst)
{
    int i = blockIdx.x * 256 + threadIdx.x;
    if (i >= 65536) return;
    const int kp = i & 7;
    int rest = i >> 3;
    const int co = rest & 63; rest >>= 6;
    const int t = rest & 3; rest >>= 2;
    const int c = rest & 7;
    const int ph = rest >> 3;
    const int ky = 2 * (t >> 1) + 1 - (ph >> 1), kx = 2 * (t & 1) + 1 - (ph & 1);
    const int ci = c * 16 + 2 * kp;
    const float* s = w + (((long)ci * 64 + co) * 16) + ky * 4 + kx;
    uint32_t lo, hi = bfsplit2(s[0], s[1024], lo);
    unsigned short* rec = dst + ((long)((ph * 8 + c) * 4 + t) * 64 + co) * 40;
    *(uint32_t*)(rec + 2 * kp) = hi;
    *(uint32_t*)(rec + 16 + 2 * kp) = lo;
}

// ---------------------------------------------------------------------------
// Generic legacy-MMA conv on 64x64 index space.
// MODE 0: stride-1 KSxKS; MODE 1: s2d stride-2 4x4 (L2); MODE 2: convT (up0).
// AIREC: input is split-bf16 records [n][CI/16][4096][64B] (RIN must be false).
// AOUT: 0 = planar only; 1 = record only (post-ROUT value);
//       2 = dual: planar v + record of relu(v).
// ---------------------------------------------------------------------------
template <int MODE, int CI, int CO, int KS, int MW, int NW, int OCC,
          bool RIN, bool ROUT, bool ADD, bool AIREC, int AOUT>
__global__ void __launch_bounds__(256, OCC) convmma(
    const float* __restrict__ in, const unsigned short* __restrict__ wb,
    const float* __restrict__ bias, const float* __restrict__ res,
    float* __restrict__ out, unsigned short* __restrict__ outrec)
{
    constexpr int CH = CI / 16;
    constexpr int T = (MODE == 0) ? KS * KS : 4;
    constexpr int PADK = (MODE == 0) ? (KS - 1) / 2 : 1;
    constexpr int MC = MW * 32;
    constexpr int NWT = CO / NW;
    constexpr int NB = NWT / 16;
    constexpr int YR = MC / 64 + 2 * PADK;
    constexpr int XW = 64 + 2 * PADK;
    constexpr int PIX = YR * XW;
    constexpr int ABYTES = (PIX * 80 + 127) & ~127;
    constexpr int BSTAGE = T * CO * 80;
    static_assert(!(AIREC && RIN), "record input cannot fuse relu");

    extern __shared__ char sm[];
    char* Abuf = sm;
    const uint32_t smA = s2u(sm);
    const uint32_t smB = s2u(sm + ABYTES);
    const int tid = threadIdx.x;
    const int lane = tid & 31;
    const int warp = tid >> 5;
    const int wm = (NW == 1) ? warp : (warp & (MW - 1));
    const int wn = (NW == 1) ? 0 : (warp >> 2);
    const int py = (MODE == 2) ? ((int)blockIdx.y >> 1) : 0;
    const int px = (MODE == 2) ? ((int)blockIdx.y & 1) : 0;
    const unsigned short* wbp = (MODE == 2) ? wb + (long)blockIdx.y * CH * T * CO * 40 : wb;
    const int mtile = blockIdx.x * MC;
    const int nimg = mtile >> 12;
    const int y0 = (mtile >> 6) & 63;
    const float* inb = in + ((long)nimg * CI << 12);
    const unsigned short* inrb = (const unsigned short*)in + ((long)nimg * CH << 12) * 32;
    const int q = lane >> 3, r = lane & 7;
    const int m_off = ((q & 1) << 3) + r;
    const int k8b = (q >> 1) * 16;

    uint32_t laneA[2];
#pragma unroll
    for (int im = 0; im < 2; im++) {
        const int mrow = wm * 32 + im * 16 + m_off;
        laneA[im] = smA + (uint32_t)((mrow >> 6) * XW + (mrow & 63)) * 80 + k8b;
    }
    const uint32_t laneBoff = (uint32_t)(wn * NWT + m_off) * 80 + k8b;

    float acc[2][2 * NB][4];
#pragma unroll
    for (int im = 0; im < 2; im++)
#pragma unroll
        for (int j = 0; j < 2 * NB; j++)
#pragma unroll
            for (int e = 0; e < 4; e++) acc[im][j][e] = 0.f;

    auto stageBall = [&](int c, int b) {
        const char* src = (const char*)(wbp + (long)c * T * CO * 40);
        const uint32_t d = smB + (uint32_t)b * BSTAGE;
        for (int i = tid; i < T * CO * 5; i += 256)
            cpa16(d + (uint32_t)i * 16, src + (long)i * 16);
    };
    auto stageA = [&](int c) {
        if (AIREC) {
            const unsigned short* cb = inrb + ((long)c << 12) * 32;
            for (int i = tid; i < PIX * 4; i += 256) {
                const int p = i >> 2, sub = i & 3;
                const int yy = p / XW, xx = p - yy * XW;
                const int iy = y0 + yy - PADK, ix = xx - PADK;
                const bool ok = (iy >= 0) & (iy < 64) & (ix >= 0) & (ix < 64);
                const char* src = (const char*)(cb + (long)(ok ? iy * 64 + ix : 0) * 32) + sub * 16;
                cpa16z(smA + (uint32_t)p * 80 + (uint32_t)sub * 16, src, ok);
            }
        } else {
            const int ci0 = c * 16;
            for (int i = tid; i < 8 * PIX; i += 256) {
                const int cp = i / PIX, p = i - cp * PIX;
                const int yy = p / XW, xx = p - yy * XW;
                const int iy = y0 + yy - PADK, ix = xx - PADK;
                float v0 = 0.f, v1 = 0.f;
                if (iy >= 0 && iy < 64 && ix >= 0 && ix < 64) {
                    const float* pp = inb + ((long)(ci0 + 2 * cp) << 12) + (iy << 6) + ix;
                    v0 = __ldg(pp); v1 = __ldg(pp + 4096);
                }
                if (RIN) { v0 = fmaxf(v0, 0.f); v1 = fmaxf(v1, 0.f); }
                uint32_t lo, hi = bfsplit2(v0, v1, lo);
                *(uint32_t*)(Abuf + p * 80 + 4 * cp) = hi;
                *(uint32_t*)(Abuf + p * 80 + 32 + 4 * cp) = lo;
            }
        }
    };

    stageBall(0, 0);
    cpacommit();
    for (int c = 0; c < CH; c++) {
        __syncthreads();
        if (AIREC) {
            stageA(c);
            cpacommit();
            if (c + 1 < CH) { stageBall(c + 1, (c + 1) & 1); cpacommit(); }
        } else {
            if (c + 1 < CH) { stageBall(c + 1, (c + 1) & 1); cpacommit(); }
            stageA(c);
        }
        if (c + 1 < CH) cpawait<1>(); else cpawait<0>();
        __syncthreads();
        const uint32_t bstage = smB + (uint32_t)(c & 1) * BSTAGE;
#pragma unroll 1
        for (int t = 0; t < T; t++) {
            int dyr, dxr;
            if (MODE == 0) { dyr = t / KS; dxr = t - (t / KS) * KS; }
            else if (MODE == 1) {
                const int pc = c >> 2;
                dyr = (t >> 1) - (pc >> 1) + 1;
                dxr = (t & 1) - (pc & 1) + 1;
            } else {
                dyr = py - (t >> 1) + 1;
                dxr = px - (t & 1) + 1;
            }
            const uint32_t dt = (uint32_t)(dyr * XW + dxr) * 80;
            uint32_t ah[2][4], al[2][4];
            ldsm4(ah[0], laneA[0] + dt);
            ldsm4(ah[1], laneA[1] + dt);
            ldsm4(al[0], laneA[0] + dt + 32);
            ldsm4(al[1], laneA[1] + dt + 32);
            const uint32_t bb = bstage + (uint32_t)t * (CO * 80) + laneBoff;
            uint32_t bf[NB][4];
#pragma unroll
            for (int nb = 0; nb < NB; nb++) ldsm4(bf[nb], bb + (uint32_t)nb * 1280);
#pragma unroll
            for (int im = 0; im < 2; im++)
#pragma unroll
                for (int nb = 0; nb < NB; nb++) {
                    mma16816(acc[im][2 * nb], ah[im], bf[nb][0], bf[nb][2]);
                    mma16816(acc[im][2 * nb + 1], ah[im], bf[nb][1], bf[nb][3]);
                    mma16816(acc[im][2 * nb], al[im], bf[nb][0], bf[nb][2]);
                    mma16816(acc[im][2 * nb + 1], al[im], bf[nb][1], bf[nb][3]);
                }
#pragma unroll
            for (int nb = 0; nb < NB; nb++) ldsm4(bf[nb], bb + (uint32_t)nb * 1280 + 32);
#pragma unroll
            for (int im = 0; im < 2; im++)
#pragma unroll
                for (int nb = 0; nb < NB; nb++) {
                    mma16816(acc[im][2 * nb], ah[im], bf[nb][0], bf[nb][2]);
                    mma16816(acc[im][2 * nb + 1], ah[im], bf[nb][1], bf[nb][3]);
                }
        }
    }

    const int gid = lane >> 2, tg = lane & 3;
    const int l0 = (mtile & 4095) + wm * 32 + gid;
#pragma unroll
    for (int im = 0; im < 2; im++) {
#pragma unroll
        for (int j = 0; j < 2 * NB; j++) {
            const int col = wn * NWT + j * 8 + 2 * tg;
            const float b0 = __ldg(bias + col), b1 = __ldg(bias + col + 1);
#pragma unroll
            for (int h = 0; h < 2; h++) {
                const int sp = l0 + im * 16 + h * 8;
                float v0 = acc[im][j][2 * h] + b0;
                float v1 = acc[im][j][2 * h + 1] + b1;
                if (MODE == 2) {
                    if (ROUT) { v0 = fmaxf(v0, 0.f); v1 = fmaxf(v1, 0.f); }
                    const long cb2 = ((long)nimg * CO + col) << 14;
                    const int oo = (((sp >> 6) * 2 + py) << 7) + ((sp & 63) * 2 + px);
                    out[cb2 + oo] = v0;
                    out[cb2 + oo + 16384] = v1;
                } else {
                    const long o0 = (((long)nimg * CO + col) << 12) + sp;
                    if (ADD) { v0 += __ldg(res + o0); v1 += __ldg(res + o0 + 4096); }
                    if (ROUT) { v0 = fmaxf(v0, 0.f); v1 = fmaxf(v1, 0.f); }
                    if (AOUT != 1) {
                        out[o0] = v0;
                        out[o0 + 4096] = v1;
                    }
                    if (AOUT >= 1) {
                        float r0 = v0, r1 = v1;
                        if (AOUT == 2) { r0 = fmaxf(r0, 0.f); r1 = fmaxf(r1, 0.f); }
                        const int ch = col >> 4, cl = col & 15;
                        unsigned short* rec = outrec +
                            ((((long)nimg * (CO / 16) + ch) << 12) + sp) * 32;
                        uint32_t lo2, hi2 = bfsplit2(r0, r1, lo2);
                        *(uint32_t*)(rec + cl) = hi2;
                        *(uint32_t*)(rec + 16 + cl) = lo2;
                    }
                }
            }
        }
    }
}

// ---------------------------------------------------------------------------
// L1 fp32 conv (CI=3), s2d output; 4x4/s2, OW=128, OHB=4.
// ---------------------------------------------------------------------------
__global__ void __launch_bounds__(256) conv_l1(
    const float* __restrict__ in, const float* __restrict__ wt,
    const float* __restrict__ bias, float* __restrict__ out)
{
    constexpr int TWIDP = 260, TILE_CI = 2600, TILE = 7800, WSTR = 49;
    extern __shared__ char smx[];
    float* tile = (float*)smx;
    ull* wp = (ull*)(smx + TILE * 4);
    const int n = blockIdx.x >> 5, rb = blockIdx.x & 31;
    const int oy0 = rb * 4, co0 = blockIdx.y * 16;
    const int tid = threadIdx.x, cog = tid & 3, spat = tid >> 2;
    const int owg = spat & 15, ohr = spat >> 4;
    const int co_l = cog * 4;
    const int iy0 = oy0 * 2 - 1;
    const float* inn = in + (long)n * 3 * 65536;

    ull acc[4][4];
#pragma unroll
    for (int c = 0; c < 4; c++) {
        const float b = __ldg(bias + co0 + co_l + c);
        const ull bb = pk2(b, b);
#pragma unroll
        for (int m = 0; m < 4; m++) acc[c][m] = bb;
    }
    {
        const uint32_t tadr = s2u(tile);
        for (int i = tid; i < TILE; i += 256) {
            const int ci_l = i / TILE_CI;
            const int rem = i - ci_l * TILE_CI;
            const int rr = rem / TWIDP, c = rem - rr * TWIDP;
            const int iy = iy0 + rr, ix = c - 1;
            const bool ok = (c < 258) & (iy >= 0) & (iy < 256) & (ix >= 0) & (ix < 256);
            const float* src = ok ? inn + ((long)ci_l * 256 + iy) * 256 + ix : inn;
            cpa4(tadr + 4u * (uint32_t)i, src, ok);
        }
        for (int i = tid; i < 16 * 48; i += 256) {
            const int c = i / 48, rem = i - c * 48;
            const float w = __ldg(wt + ((long)(co0 + c) * 3 + rem / 16) * 16 + rem % 16);
            wp[c * WSTR + rem] = pk2(w, w);
        }
        cpacommit(); cpawait<0>();
        __syncthreads();
    }
#pragma unroll 1
    for (int ci_l = 0; ci_l < 3; ci_l++) {
        const float* tci = tile + ci_l * TILE_CI;
#pragma unroll
        for (int kh = 0; kh < 4; kh++) {
            const float* trow = tci + (ohr * 2 + kh) * TWIDP + owg * 16;
            float ir[18];
#pragma unroll
            for (int v = 0; v < 4; v++) {
                const float4 q4 = reinterpret_cast<const float4*>(trow)[v];
                ir[4 * v] = q4.x; ir[4 * v + 1] = q4.y; ir[4 * v + 2] = q4.z; ir[4 * v + 3] = q4.w;
            }
            ir[16] = trow[16]; ir[17] = trow[17];
#pragma unroll
            for (int kw = 0; kw < 4; kw++) {
                ull p[4];
#pragma unroll
                for (int m = 0; m < 4; m++)
                    p[m] = pk2(ir[4 * m + kw], ir[4 * m + 2 + kw]);
#pragma unroll
                for (int c = 0; c < 4; c++) {
                    const ull w2 = wp[(co_l + c) * WSTR + ci_l * 16 + kh * 4 + kw];
#pragma unroll
                    for (int m = 0; m < 4; m++) fma2(acc[c][m], p[m], w2);
                }
            }
        }
    }
    const int oy = oy0 + ohr;
#pragma unroll
    for (int c = 0; c < 4; c++) {
        float o[8];
#pragma unroll
        for (int m = 0; m < 4; m++) {
            const float2 t = upk(acc[c][m]);
            o[2 * m] = fmaxf(t.x, 0.f); o[2 * m + 1] = fmaxf(t.y, 0.f);
        }
        const int pyl = oy & 1, yh = oy >> 1, xh0 = owg * 4;
        const int ch = co0 + co_l + c;
        float* p0 = out + (((long)n * 256 + (pyl * 2 + 0) * 64 + ch) << 12) + (yh << 6) + xh0;
        float* p1 = out + (((long)n * 256 + (pyl * 2 + 1) * 64 + ch) << 12) + (yh << 6) + xh0;
        *reinterpret_cast<float4*>(p0) = make_float4(o[0], o[2], o[4], o[6]);
        *reinterpret_cast<float4*>(p1) = make_float4(o[1], o[3], o[5], o[7]);
    }
}

// ---------------------------------------------------------------------------
// up1 fp32 conv-T (64 -> 3, 128->256)
// ---------------------------------------------------------------------------
__global__ void __launch_bounds__(256) convt_up1(
    const float* __restrict__ in, const float* __restrict__ wt,
    const float* __restrict__ bias, float* __restrict__ out)
{
    constexpr int TWIDP = 132, TILE_CI = 792, TILE = 6336, WTSTR = 129;
    constexpr int STRIDEB = TILE * 4 + 2 * WTSTR * 8;
    extern __shared__ char smx[];
    const int n = blockIdx.x >> 5, rb = blockIdx.x & 31;
    const int oy0 = rb * 8;
    const int tid = threadIdx.x;
    const int owg = tid & 31, ohr = tid >> 5;
    const int iy0 = oy0 / 2 - 1;
    const int oy = oy0 + ohr;
    const int ky0 = (oy + 1) & 1;
    const float* inn = in + (long)n * 64 * 16384;

    ull accp[2][8];
#pragma unroll
    for (int qq = 0; qq < 2; qq++) {
        const int c0 = 2 * qq;
        const float b0 = (c0 < 3) ? __ldg(bias + c0) : 0.f;
        const float b1 = (c0 + 1 < 3) ? __ldg(bias + c0 + 1) : 0.f;
        const ull bb = pk2(b0, b1);
#pragma unroll
        for (int j = 0; j < 8; j++) accp[qq][j] = bb;
    }
    auto stage = [&](int gidx, int bi) {
        char* buf = smx + bi * STRIDEB;
        float* tile = (float*)buf;
        ull* wp = (ull*)(buf + TILE * 4);
        const uint32_t tadr = s2u(tile);
        const int ci0 = gidx * 8;
        for (int i = tid; i < TILE; i += 256) {
            const int ci_l = i / TILE_CI;
            const int rem = i - ci_l * TILE_CI;
            const int rr = rem / TWIDP, c = rem - rr * TWIDP;
            const int iy = iy0 + rr, ix = c - 1;
            const bool ok = (c < 130) & (iy >= 0) & (iy < 128) & (ix >= 0) & (ix < 128);
            const float* src = ok ? inn + ((long)(ci0 + ci_l) * 128 + iy) * 128 + ix : inn;
            cpa4(tadr + 4u * (uint32_t)i, src, ok);
        }
        for (int i = tid; i < 2 * 128; i += 256) {
            const int cpg = i >> 7, rem = i & 127;
            const int ci_l = rem >> 4, tap = rem & 15;
            const int c0 = 2 * cpg;
            const float w0 = (c0 < 3) ? __ldg(wt + ((long)(ci0 + ci_l) * 3 + c0) * 16 + tap) : 0.f;
            const float w1 = (c0 + 1 < 3) ? __ldg(wt + ((long)(ci0 + ci_l) * 3 + c0 + 1) * 16 + tap) : 0.f;
            wp[cpg * WTSTR + rem] = pk2(w0, w1);
        }
    };
    stage(0, 0);
    cpacommit();
    for (int g = 0; g < 8; g++) {
        const int bi = g & 1;
        if (g + 1 < 8) { stage(g + 1, bi ^ 1); cpacommit(); cpawait<1>(); }
        else cpawait<0>();
        __syncthreads();
        const float* tb = (const float*)(smx + bi * STRIDEB);
        const ull* wbp = (const ull*)(smx + bi * STRIDEB + TILE * 4);
#pragma unroll 1
        for (int ci_l = 0; ci_l < 8; ci_l++) {
            const float* tci = tb + ci_l * TILE_CI;
#pragma unroll
            for (int t2 = 0; t2 < 2; t2++) {
                const int ky = ky0 + 2 * t2;
                const int rr = ((oy + 1 - ky) >> 1) - iy0;
                const float* trow = tci + rr * TWIDP + owg * 4;
                float ir[6];
                {
                    const float4 q4 = *reinterpret_cast<const float4*>(trow);
                    ir[0] = q4.x; ir[1] = q4.y; ir[2] = q4.z; ir[3] = q4.w;
                    ir[4] = trow[4]; ir[5] = trow[5];
                }
#pragma unroll
                for (int kx = 0; kx < 4; kx++) {
                    const int ph = (kx + 1) & 1;
                    const int dt = (kx == 0) ? 1 : ((kx == 3) ? -1 : 0);
                    ull vv[4];
#pragma unroll
                    for (int m = 0; m < 4; m++) {
                        const float v = ir[m + dt + 1];
                        vv[m] = pk2(v, v);
                    }
#pragma unroll
                    for (int qq = 0; qq < 2; qq++) {
                        const ull w2 = wbp[qq * WTSTR + ci_l * 16 + ky * 4 + kx];
#pragma unroll
                        for (int m = 0; m < 4; m++) fma2(accp[qq][2 * m + ph], vv[m], w2);
                    }
                }
            }
        }
        __syncthreads();
    }
#pragma unroll
    for (int qq = 0; qq < 2; qq++) {
        float o0[8], o1[8];
#pragma unroll
        for (int j = 0; j < 8; j++) {
            const float2 t = upk(accp[qq][j]);
            o0[j] = t.x; o1[j] = t.y;
        }
        const int c0 = 2 * qq, c1 = c0 + 1;
        if (c0 < 3) {
            float* op = out + (((long)n * 3 + c0) * 256 + oy) * 256 + owg * 8;
            reinterpret_cast<float4*>(op)[0] = make_float4(o0[0], o0[1], o0[2], o0[3]);
            reinterpret_cast<float4*>(op)[1] = make_float4(o0[4], o0[5], o0[6], o0[7]);
        }
        if (c1 < 3) {
            float* op = out + (((long)n * 3 + c1) * 256 + oy) * 256 + owg * 8;
            reinterpret_cast<float4*>(op)[0] = make_float4(o1[0], o1[1], o1[2], o1[3]);
            reinterpret_cast<float4*>(op)[1] = make_float4(o1[4], o1[5], o1[6], o1[7]);
        }
    }
}

// ---------------------------------------------------------------------------
// VQ
// ---------------------------------------------------------------------------
__global__ void __launch_bounds__(256) vqk2(
    const float* __restrict__ z, const float* __restrict__ cb, float* __restrict__ q)
{
    constexpr int NPIX = 4096;
    __shared__ float cbs[128][68];
    __shared__ float cns[128];
    const int tid = threadIdx.x;
    const int p = blockIdx.x * 256 + tid;
    const int b = p >> 12;
    const int pix = p & 4095;
    const float* zp = z + (long)b * 64 * NPIX + pix;
    float f[64];
#pragma unroll
    for (int d = 0; d < 64; d++) f[d] = zp[(long)d * NPIX];
    ull fp[32];
#pragma unroll
    for (int i = 0; i < 32; i++) fp[i] = pk2(f[2 * i], f[2 * i + 1]);
    float best = 3.4e38f;
    int bidx = 0;
    for (int t = 0; t < 4; t++) {
        __syncthreads();
        for (int i = tid; i < 8192; i += 256) {
            const int d = i >> 7, kk = i & 127;
            cbs[kk][d] = __ldg(cb + d * 512 + t * 128 + kk);
        }
        __syncthreads();
        if (tid < 128) {
            const float* row = cbs[tid];
            float s = 0.f;
#pragma unroll
            for (int d = 0; d < 64; d++) s += row[d] * row[d];
            cns[tid] = s;
        }
        __syncthreads();
        for (int kk = 0; kk < 128; kk++) {
            const ulonglong2* row = reinterpret_cast<const ulonglong2*>(cbs[kk]);
            ull a0 = 0, a1 = 0, a2 = 0, a3 = 0;
#pragma unroll
            for (int i = 0; i < 16; i += 2) {
                const ulonglong2 u = row[i];
                const ulonglong2 v = row[i + 1];
                fma2(a0, u.x, fp[2 * i]);
                fma2(a1, u.y, fp[2 * i + 1]);
                fma2(a2, v.x, fp[2 * i + 2]);
                fma2(a3, v.y, fp[2 * i + 3]);
            }
            const float2 x0 = upk(a0), x1 = upk(a1), x2 = upk(a2), x3 = upk(a3);
            const float dot = ((x0.x + x0.y) + (x1.x + x1.y)) + ((x2.x + x2.y) + (x3.x + x3.y));
            const float dist = cns[kk] - 2.f * dot;
            if (dist < best) { best = dist; bidx = t * 128 + kk; }
        }
    }
    float* qp = q + (long)b * 64 * NPIX + pix;
#pragma unroll
    for (int d = 0; d < 64; d++) qp[(long)d * NPIX] = __ldg(cb + d * 512 + bidx);
}

// ---------------------------------------------------------------------------
// Host launcher
// ---------------------------------------------------------------------------
extern "C" void kernel_launch(void* const* d_in, const int* in_sizes, int n_in,
                              void* d_out, int out_size)
{
    (void)in_sizes; (void)n_in; (void)out_size;
    const float* x        = (const float*)d_in[0];
    const float* enc_w0   = (const float*)d_in[1];
    const float* enc_b0   = (const float*)d_in[2];
    const float* enc_w1   = (const float*)d_in[3];
    const float* enc_b1   = (const float*)d_in[4];
    const float* enc_wf   = (const float*)d_in[5];
    const float* enc_bf   = (const float*)d_in[6];
    const float* enc_rw1  = (const float*)d_in[7];
    const float* enc_rb1  = (const float*)d_in[8];
    const float* enc_rw2  = (const float*)d_in[9];
    const float* enc_rb2  = (const float*)d_in[10];
    const float* pre_w    = (const float*)d_in[11];
    const float* pre_b    = (const float*)d_in[12];
    const float* codebook = (const float*)d_in[13];
    const float* dec_w    = (const float*)d_in[14];
    const float* dec_b    = (const float*)d_in[15];
    const float* dec_rw1  = (const float*)d_in[16];
    const float* dec_rb1  = (const float*)d_in[17];
    const float* dec_rw2  = (const float*)d_in[18];
    const float* dec_rb2  = (const float*)d_in[19];
    const float* up_w0    = (const float*)d_in[20];
    const float* up_b0    = (const float*)d_in[21];
    const float* up_w1    = (const float*)d_in[22];
    const float* up_b1    = (const float*)d_in[23];
    float* out = (float*)d_out;

    float *pA, *pB, *pC, *pT, *pZ, *pQ, *pS;
    unsigned short* pW;
    cudaGetSymbolAddress((void**)&pA, g_bufA);
    cudaGetSymbolAddress((void**)&pB, g_bufB);
    cudaGetSymbolAddress((void**)&pC, g_bufC);
    cudaGetSymbolAddress((void**)&pT, g_bufT);
    cudaGetSymbolAddress((void**)&pZ, g_bufZ);
    cudaGetSymbolAddress((void**)&pQ, g_bufQ);
    cudaGetSymbolAddress((void**)&pS, g_bufS);
    cudaGetSymbolAddress((void**)&pW, g_wb);
    unsigned short* pR = (unsigned short*)pS;   // record buffer (reuses bufS after L2)
    unsigned short* pBr = (unsigned short*)pB;  // L2 writes records directly into pB
    unsigned short* pTr = (unsigned short*)pT;

    // g_wb offsets (shorts)
    const int oWF = 0;
    const int oER1a = 368640, oER1b = 460800;
    const int oER2a = 552960, oER2b = 563200;
    const int oPRE = 573440;
    const int oDEC = 593920;
    const int oDR1a = 778240, oDR1b = 870400;
    const int oDR2a = 962560, oDR2b = 972800;
    const int oL2  = 983040;
    const int oUP0 = 1310720;

    cudaFuncSetAttribute((const void*)convmma<1,256,128,0,4,2,2,false,true,false,false,1>,
        cudaFuncAttributeMaxDynamicSharedMemorySize, cmma_smem(128,4,1,4));
    cudaFuncSetAttribute((const void*)convmma<0,128,128,3,4,2,1,false,false,false,true,2>,
        cudaFuncAttributeMaxDynamicSharedMemorySize, cmma_smem(128,9,1,4));
    cudaFuncSetAttribute((const void*)convmma<0,64,128,3,4,2,1,false,false,false,false,2>,
        cudaFuncAttributeMaxDynamicSharedMemorySize, cmma_smem(128,9,1,4));
    cudaFuncSetAttribute((const void*)convmma<0,128,32,3,8,1,2,false,true,false,true,1>,
        cudaFuncAttributeMaxDynamicSharedMemorySize, cmma_smem(32,9,1,8));
    cudaFuncSetAttribute((const void*)convmma<2,128,64,0,4,2,2,false,true,false,true,0>,
        cudaFuncAttributeMaxDynamicSharedMemorySize, cmma_smem(64,4,1,4));
    cudaFuncSetAttribute((const void*)convt_up1,
        cudaFuncAttributeMaxDynamicSharedMemorySize, 2 * (6336*4 + 2*129*8));

    // batched weight prep
    PrepJobs jobs;
    auto J = [&](int k, const float* w, int off, int CI, int CO, int KS) {
        jobs.j[k] = PrepJob{w, off, CI, CO, KS, (CI / 16) * KS * KS * CO * 8};
    };
    J(0, enc_wf, oWF, 128, 128, 3);
    J(1, enc_rw1, oER1a, 128, 32, 3);
    J(2, enc_rw1 + (long)32 * 128 * 9, oER1b, 128, 32, 3);
    J(3, enc_rw2, oER2a, 32, 128, 1);
    J(4, enc_rw2 + (long)128 * 32, oER2b, 32, 128, 1);
    J(5, pre_w, oPRE, 128, 64, 1);
    J(6, dec_w, oDEC, 64, 128, 3);
    J(7, dec_rw1, oDR1a, 128, 32, 3);
    J(8, dec_rw1 + (long)32 * 128 * 9, oDR1b, 128, 32, 3);
    J(9, dec_rw2, oDR2a, 32, 128, 1);
    J(10, dec_rw2 + (long)128 * 32, oDR2b, 32, 128, 1);
    prepw_all<<<dim3(288, 11), 256>>>(jobs, pW);
    prepw_s2d<<<256, 256>>>(enc_w1, pW + oL2);
    prepw_ct<<<256, 256>>>(up_w0, pW + oUP0);

    // L1 fp32 -> s2d layout in bufS
    conv_l1<<<dim3(512, 4), 256, 7800*4 + 16*49*8>>>(x, enc_w0, enc_b0, pS);
    // L2 (s2d) -> pB records (relu fused)
    convmma<1,256,128,0,4,2,2,false,true,false,false,1><<<512, 256, cmma_smem(128,4,1,4)>>>(
        pS, pW + oL2, enc_b1, nullptr, pB, pBr);
    // enc_wf: record-in (pB) -> pC planar + pR record(relu)
    convmma<0,128,128,3,4,2,1,false,false,false,true,2><<<512, 256, cmma_smem(128,9,1,4)>>>(
        pB, pW + oWF, enc_bf, nullptr, pC, pR);
    // enc res blocks: 3x3 record-in (pR) relu-out -> pT record; 1x1 record-in + ADD -> dual
    convmma<0,128,32,3,8,1,2,false,true,false,true,1><<<256, 256, cmma_smem(32,9,1,8)>>>(
        (const float*)pR, pW + oER1a, enc_rb1, nullptr, pT, pTr);
    convmma<0,32,128,1,4,2,2,false,false,true,true,2><<<512, 256, cmma_smem(128,1,0,4)>>>(
        pT, pW + oER2a, enc_rb2, pC, pC, pR);
    convmma<0,128,32,3,8,1,2,false,true,false,true,1><<<256, 256, cmma_smem(32,9,1,8)>>>(
        (const float*)pR, pW + oER1b, enc_rb1 + 32, nullptr, pT, pTr);
    convmma<0,32,128,1,4,2,2,false,false,true,true,2><<<512, 256, cmma_smem(128,1,0,4)>>>(
        pT, pW + oER2b, enc_rb2 + 128, pC, pC, pR);
    // pre: record-in (pR) -> bufZ planar
    convmma<0,128,64,1,4,2,2,false,false,false,true,0><<<512, 256, cmma_smem(64,1,0,4)>>>(
        (const float*)pR, pW + oPRE, pre_b, nullptr, pZ, nullptr);

    vqk2<<<256, 256>>>(pZ, codebook, pQ);

    // dec conv (planar in) -> pB planar + pR record(relu)
    convmma<0,64,128,3,4,2,1,false,false,false,false,2><<<512, 256, cmma_smem(128,9,1,4)>>>(
        pQ, pW + oDEC, dec_b, nullptr, pB, pR);
    // dec res blocks
    convmma<0,128,32,3,8,1,2,false,true,false,true,1><<<256, 256, cmma_smem(32,9,1,8)>>>(
        (const float*)pR, pW + oDR1a, dec_rb1, nullptr, pT, pTr);
    convmma<0,32,128,1,4,2,2,false,false,true,true,2><<<512, 256, cmma_smem(128,1,0,4)>>>(
        pT, pW + oDR2a, dec_rb2, pB, pB, pR);
    convmma<0,128,32,3,8,1,2,false,true,false,true,1><<<256, 256, cmma_smem(32,9,1,8)>>>(
        (const float*)pR, pW + oDR1b, dec_rb1 + 32, nullptr, pT, pTr);
    convmma<0,32,128,1,4,2,2,false,false,true,true,2><<<512, 256, cmma_smem(128,1,0,4)>>>(
        pT, pW + oDR2b, dec_rb2 + 128, pB, pB, pR);
    // up0: record-in (pR), convT phases, relu-out -> bufA planar
    convmma<2,128,64,0,4,2,2,false,true,false,true,0><<<dim3(512, 4), 256, cmma_smem(64,4,1,4)>>>(
        (const float*)pR, pW + oUP0, up_b0, nullptr, pA, nullptr);
    // up1 fp32 -> out
    convt_up1<<<512, 256, 2 * (6336*4 + 2*129*8)>>>(pA, up_w1, up_b1, out);
}